// round 3
// baseline (speedup 1.0000x reference)
#include <cuda_runtime.h>
#include <math.h>

#define N_NODES  100000
#define N_EDGES  1600000
#define DIM      128
#define NCLS     40

// Scratch (no allocation allowed) — g_agg reused for both layers.
__device__ float g_agg[(size_t)N_NODES * DIM];
__device__ float g_x1[(size_t)N_NODES * DIM];

// ---------------------------------------------------------------------------
// Init: agg = x  (so agg accumulates to segment_sum + x directly)
// ---------------------------------------------------------------------------
__global__ void copy_kernel(const float* __restrict__ src, float* __restrict__ dst, int n4) {
    int i = blockIdx.x * blockDim.x + threadIdx.x;
    if (i < n4) ((float4*)dst)[i] = ((const float4*)src)[i];
}

// ---------------------------------------------------------------------------
// Scatter: one warp per edge. 32 lanes x float4 = 128 floats.
// red.global.add.v4.f32 — vectorized no-return reduction (sm_90+).
// ---------------------------------------------------------------------------
__global__ void scatter_kernel(const float* __restrict__ x,
                               const int2* __restrict__ edges,
                               float* __restrict__ agg) {
    int gw   = (blockIdx.x * blockDim.x + threadIdx.x) >> 5;
    int lane = threadIdx.x & 31;
    if (gw >= N_EDGES) return;
    int2 e = __ldg(&edges[gw]);                       // e.x = src, e.y = dst
    float4 v = __ldg(((const float4*)(x + (size_t)e.x * DIM)) + lane);
    float* o = agg + (size_t)e.y * DIM + lane * 4;
    asm volatile("red.global.add.v4.f32 [%0], {%1, %2, %3, %4};"
                 :: "l"(o), "f"(v.x), "f"(v.y), "f"(v.z), "f"(v.w) : "memory");
}

// ---------------------------------------------------------------------------
// Layer-1 fused MLP: Y = relu( relu(X*Wa + ba) * Wb + bb ), all 128x128.
// Block = 256 threads, 64 rows. Micro-tile 4 rows x 8 cols per thread.
// Both weight matrices staged in smem; H tile round-trips through the X tile.
// ---------------------------------------------------------------------------
#define L1_SMEM_FLOATS (64*132 + 128*128 + 128*128)

__global__ void __launch_bounds__(256, 1)
gin_mlp128_kernel(const float* __restrict__ X,
                  const float* __restrict__ Wa, const float* __restrict__ ba,
                  const float* __restrict__ Wb, const float* __restrict__ bb,
                  float* __restrict__ Y) {
    extern __shared__ float sm[];
    float* Xs  = sm;                // [64][132] padded
    float* Was = sm + 64 * 132;     // [128][128]
    float* Wbs = Was + 128 * 128;   // [128][128]

    const int tid  = threadIdx.x;
    const int cg   = tid & 15;      // col group: cols [cg*8, cg*8+8)
    const int rg   = tid >> 4;      // row group: rows [rg*4, rg*4+4)
    const int base = blockIdx.x * 64;

    // Load X tile (coalesced), zero-fill OOB rows.
    for (int idx = tid; idx < 64 * 32; idx += 256) {
        int r = idx >> 5, c4 = idx & 31;
        int row = base + r;
        float4 v = (row < N_NODES)
                       ? __ldg(((const float4*)(X + (size_t)row * DIM)) + c4)
                       : make_float4(0.f, 0.f, 0.f, 0.f);
        *(float4*)(Xs + r * 132 + c4 * 4) = v;   // 132*4 and c4*16 both 16B-multiples
    }
    // Load both weight matrices.
    for (int idx = tid; idx < 4096; idx += 256) {
        ((float4*)Was)[idx] = __ldg(((const float4*)Wa) + idx);
        ((float4*)Wbs)[idx] = __ldg(((const float4*)Wb) + idx);
    }
    __syncthreads();

    float acc[4][8];

    // ---- stage 1: H = relu(X*Wa + ba) ----
    #pragma unroll
    for (int j = 0; j < 8; j++) {
        float b = __ldg(ba + cg * 8 + j);
        #pragma unroll
        for (int i = 0; i < 4; i++) acc[i][j] = b;
    }
    #pragma unroll 4
    for (int k = 0; k < 128; k++) {
        float4 w0 = *(float4*)(Was + k * 128 + cg * 8);
        float4 w1 = *(float4*)(Was + k * 128 + cg * 8 + 4);
        float xv[4];
        #pragma unroll
        for (int i = 0; i < 4; i++) xv[i] = Xs[(rg * 4 + i) * 132 + k];
        #pragma unroll
        for (int i = 0; i < 4; i++) {
            acc[i][0] += xv[i] * w0.x;  acc[i][1] += xv[i] * w0.y;
            acc[i][2] += xv[i] * w0.z;  acc[i][3] += xv[i] * w0.w;
            acc[i][4] += xv[i] * w1.x;  acc[i][5] += xv[i] * w1.y;
            acc[i][6] += xv[i] * w1.z;  acc[i][7] += xv[i] * w1.w;
        }
    }
    __syncthreads();   // all reads of Xs done
    #pragma unroll
    for (int i = 0; i < 4; i++) {
        float4 a0 = make_float4(fmaxf(acc[i][0],0.f), fmaxf(acc[i][1],0.f),
                                fmaxf(acc[i][2],0.f), fmaxf(acc[i][3],0.f));
        float4 a1 = make_float4(fmaxf(acc[i][4],0.f), fmaxf(acc[i][5],0.f),
                                fmaxf(acc[i][6],0.f), fmaxf(acc[i][7],0.f));
        *(float4*)(Xs + (rg * 4 + i) * 132 + cg * 8)     = a0;
        *(float4*)(Xs + (rg * 4 + i) * 132 + cg * 8 + 4) = a1;
    }
    __syncthreads();

    // ---- stage 2: Y = relu(H*Wb + bb) ----
    #pragma unroll
    for (int j = 0; j < 8; j++) {
        float b = __ldg(bb + cg * 8 + j);
        #pragma unroll
        for (int i = 0; i < 4; i++) acc[i][j] = b;
    }
    #pragma unroll 4
    for (int k = 0; k < 128; k++) {
        float4 w0 = *(float4*)(Wbs + k * 128 + cg * 8);
        float4 w1 = *(float4*)(Wbs + k * 128 + cg * 8 + 4);
        float xv[4];
        #pragma unroll
        for (int i = 0; i < 4; i++) xv[i] = Xs[(rg * 4 + i) * 132 + k];
        #pragma unroll
        for (int i = 0; i < 4; i++) {
            acc[i][0] += xv[i] * w0.x;  acc[i][1] += xv[i] * w0.y;
            acc[i][2] += xv[i] * w0.z;  acc[i][3] += xv[i] * w0.w;
            acc[i][4] += xv[i] * w1.x;  acc[i][5] += xv[i] * w1.y;
            acc[i][6] += xv[i] * w1.z;  acc[i][7] += xv[i] * w1.w;
        }
    }
    #pragma unroll
    for (int i = 0; i < 4; i++) {
        int row = base + rg * 4 + i;
        if (row < N_NODES) {
            float4 a0 = make_float4(fmaxf(acc[i][0],0.f), fmaxf(acc[i][1],0.f),
                                    fmaxf(acc[i][2],0.f), fmaxf(acc[i][3],0.f));
            float4 a1 = make_float4(fmaxf(acc[i][4],0.f), fmaxf(acc[i][5],0.f),
                                    fmaxf(acc[i][6],0.f), fmaxf(acc[i][7],0.f));
            *(float4*)(Y + (size_t)row * DIM + cg * 8)     = a0;
            *(float4*)(Y + (size_t)row * DIM + cg * 8 + 4) = a1;
        }
    }
}

// ---------------------------------------------------------------------------
// Layer-2 fused: out = softmax( relu(X*W2a + b2a) * W2b + b2b ).
// Block = 128 threads, one row per thread; X tile staged coalesced with
// pad-129 (bank-conflict-free per-row reads). Weight reads are broadcasts.
// ---------------------------------------------------------------------------
#define L2_SMEM_FLOATS (128*129 + 128*40 + 40*40)

__global__ void __launch_bounds__(128)
layer2_kernel(const float* __restrict__ X,
              const float* __restrict__ Wa, const float* __restrict__ ba,
              const float* __restrict__ Wb, const float* __restrict__ bb,
              float* __restrict__ out) {
    extern __shared__ float sm[];
    float* Xs  = sm;                 // [128][129]
    float* Was = sm + 128 * 129;     // [128][40]
    float* Wbs = Was + 128 * 40;     // [40][40]

    const int tid  = threadIdx.x;
    const int base = blockIdx.x * 128;

    for (int idx = tid; idx < 128 * 32; idx += 128) {
        int r = idx >> 5, c4 = idx & 31;
        int row = base + r;
        float4 v = (row < N_NODES)
                       ? __ldg(((const float4*)(X + (size_t)row * DIM)) + c4)
                       : make_float4(0.f, 0.f, 0.f, 0.f);
        float* d = Xs + r * 129 + c4 * 4;   // unaligned rows -> scalar stores
        d[0] = v.x; d[1] = v.y; d[2] = v.z; d[3] = v.w;
    }
    for (int idx = tid; idx < (128 * 40) / 4; idx += 128)
        ((float4*)Was)[idx] = __ldg(((const float4*)Wa) + idx);
    for (int idx = tid; idx < (40 * 40) / 4; idx += 128)
        ((float4*)Wbs)[idx] = __ldg(((const float4*)Wb) + idx);
    __syncthreads();

    const int row = base + tid;

    float z[NCLS];
    #pragma unroll
    for (int c = 0; c < NCLS; c++) z[c] = __ldg(ba + c);

    for (int k = 0; k < 128; k++) {
        float xv = Xs[tid * 129 + k];
        #pragma unroll
        for (int c4 = 0; c4 < 10; c4++) {
            float4 w = *(float4*)(Was + k * 40 + c4 * 4);   // broadcast
            z[c4*4+0] += xv * w.x;  z[c4*4+1] += xv * w.y;
            z[c4*4+2] += xv * w.z;  z[c4*4+3] += xv * w.w;
        }
    }
    #pragma unroll
    for (int c = 0; c < NCLS; c++) z[c] = fmaxf(z[c], 0.f);

    float lg[NCLS];
    #pragma unroll
    for (int c = 0; c < NCLS; c++) lg[c] = __ldg(bb + c);
    #pragma unroll 4
    for (int j = 0; j < NCLS; j++) {
        float zv = z[j];
        #pragma unroll
        for (int c4 = 0; c4 < 10; c4++) {
            float4 w = *(float4*)(Wbs + j * 40 + c4 * 4);   // broadcast
            lg[c4*4+0] += zv * w.x;  lg[c4*4+1] += zv * w.y;
            lg[c4*4+2] += zv * w.z;  lg[c4*4+3] += zv * w.w;
        }
    }

    // softmax
    float m = lg[0];
    #pragma unroll
    for (int c = 1; c < NCLS; c++) m = fmaxf(m, lg[c]);
    float s = 0.f;
    #pragma unroll
    for (int c = 0; c < NCLS; c++) { lg[c] = expf(lg[c] - m); s += lg[c]; }
    float inv = 1.f / s;

    if (row < N_NODES) {
        #pragma unroll
        for (int c4 = 0; c4 < 10; c4++) {
            float4 v = make_float4(lg[c4*4+0]*inv, lg[c4*4+1]*inv,
                                   lg[c4*4+2]*inv, lg[c4*4+3]*inv);
            *(float4*)(out + (size_t)row * NCLS + c4 * 4) = v;   // 160B row stride, 16B-aligned
        }
    }
}

// ---------------------------------------------------------------------------
extern "C" void kernel_launch(void* const* d_in, const int* in_sizes, int n_in,
                              void* d_out, int out_size) {
    const float* x   = (const float*)d_in[0];
    const int*   ei  = (const int*)  d_in[1];
    const float* W1a = (const float*)d_in[2];
    const float* b1a = (const float*)d_in[3];
    const float* W1b = (const float*)d_in[4];
    const float* b1b = (const float*)d_in[5];
    const float* W2a = (const float*)d_in[6];
    const float* b2a = (const float*)d_in[7];
    const float* W2b = (const float*)d_in[8];
    const float* b2b = (const float*)d_in[9];
    float* out = (float*)d_out;

    float *agg = nullptr, *x1 = nullptr;
    cudaGetSymbolAddress((void**)&agg, g_agg);
    cudaGetSymbolAddress((void**)&x1,  g_x1);

    const size_t l1_smem = L1_SMEM_FLOATS * sizeof(float);
    const size_t l2_smem = L2_SMEM_FLOATS * sizeof(float);
    cudaFuncSetAttribute(gin_mlp128_kernel, cudaFuncAttributeMaxDynamicSharedMemorySize, (int)l1_smem);
    cudaFuncSetAttribute(layer2_kernel,     cudaFuncAttributeMaxDynamicSharedMemorySize, (int)l2_smem);

    const int n4          = N_NODES * DIM / 4;           // 3,200,000
    const int copy_blocks = (n4 + 255) / 256;
    const int scat_blocks = (N_EDGES + 7) / 8;           // 8 warps/block
    const int mlp_blocks  = (N_NODES + 63) / 64;
    const int l2_blocks   = (N_NODES + 127) / 128;

    // Layer 1
    copy_kernel   <<<copy_blocks, 256>>>(x, agg, n4);
    scatter_kernel<<<scat_blocks, 256>>>(x, (const int2*)ei, agg);
    gin_mlp128_kernel<<<mlp_blocks, 256, l1_smem>>>(agg, W1a, b1a, W1b, b1b, x1);

    // Layer 2
    copy_kernel   <<<copy_blocks, 256>>>(x1, agg, n4);
    scatter_kernel<<<scat_blocks, 256>>>(x1, (const int2*)ei, agg);
    layer2_kernel <<<l2_blocks, 128, l2_smem>>>(agg, W2a, b2a, W2b, b2b, out);
}

// round 5
// speedup vs baseline: 1.4511x; 1.4511x over previous
#include <cuda_runtime.h>
#include <math.h>

#define N_NODES  100000
#define N_EDGES  1600000
#define DIM      128
#define NCLS     40
#define NB       ((N_NODES + 255) / 256)   // 391 scan blocks

typedef unsigned long long u64;

// Scratch (no allocation allowed)
__device__ float g_agg[(size_t)N_NODES * DIM];
__device__ float g_x1 [(size_t)N_NODES * DIM];
__device__ int   g_deg[N_NODES];
__device__ int   g_start[N_NODES];
__device__ int   g_cursor[N_NODES];
__device__ int   g_blocksum[NB];
__device__ int   g_col[N_EDGES];

// ---------------------------------------------------------------------------
// f32x2 helpers (sm_103a packed fp32 FMA — 2x scalar FFMA throughput)
// ---------------------------------------------------------------------------
__device__ __forceinline__ u64 bcast2(float v) {
    u64 r; asm("mov.b64 %0, {%1, %2};" : "=l"(r) : "f"(v), "f"(v)); return r;
}
__device__ __forceinline__ void ffma2(u64& d, u64 a, u64 b) {
    asm("fma.rn.f32x2 %0, %1, %2, %0;" : "+l"(d) : "l"(a), "l"(b));
}
__device__ __forceinline__ float2 unpk(u64 v) {
    float lo, hi; asm("mov.b64 {%0, %1}, %2;" : "=f"(lo), "=f"(hi) : "l"(v));
    return make_float2(lo, hi);
}

// ---------------------------------------------------------------------------
// CSR build: degree count -> 2-level exclusive scan -> fill
// ---------------------------------------------------------------------------
__global__ void zero_deg_kernel() {
    int i = blockIdx.x * blockDim.x + threadIdx.x;
    if (i < N_NODES) g_deg[i] = 0;
}

__global__ void count_kernel(const int2* __restrict__ edges) {
    int i = blockIdx.x * blockDim.x + threadIdx.x;
    if (i < N_EDGES) atomicAdd(&g_deg[__ldg(&edges[i]).y], 1);
}

__global__ void block_sum_kernel() {
    __shared__ int sm[256];
    int i = blockIdx.x * 256 + threadIdx.x;
    sm[threadIdx.x] = (i < N_NODES) ? g_deg[i] : 0;
    __syncthreads();
    for (int s = 128; s > 0; s >>= 1) {
        if (threadIdx.x < s) sm[threadIdx.x] += sm[threadIdx.x + s];
        __syncthreads();
    }
    if (threadIdx.x == 0) g_blocksum[blockIdx.x] = sm[0];
}

__global__ void top_scan_kernel() {   // 1 block, 512 threads, NB=391 <= 512
    __shared__ int sm[512];
    int t = threadIdx.x;
    sm[t] = (t < NB) ? g_blocksum[t] : 0;
    __syncthreads();
    for (int off = 1; off < 512; off <<= 1) {
        int v = (t >= off) ? sm[t - off] : 0;
        __syncthreads();
        sm[t] += v;
        __syncthreads();
    }
    if (t < NB) g_blocksum[t] = (t == 0) ? 0 : sm[t - 1];   // exclusive
}

__global__ void final_scan_kernel() {
    __shared__ int sm[256];
    int t = threadIdx.x;
    int i = blockIdx.x * 256 + t;
    int d = (i < N_NODES) ? g_deg[i] : 0;
    sm[t] = d;
    __syncthreads();
    for (int off = 1; off < 256; off <<= 1) {
        int v = (t >= off) ? sm[t - off] : 0;
        __syncthreads();
        sm[t] += v;
        __syncthreads();
    }
    if (i < N_NODES) {
        int excl = sm[t] - d + g_blocksum[blockIdx.x];
        g_start[i]  = excl;
        g_cursor[i] = excl;
    }
}

__global__ void fill_kernel(const int2* __restrict__ edges) {
    int i = blockIdx.x * blockDim.x + threadIdx.x;
    if (i < N_EDGES) {
        int2 e = __ldg(&edges[i]);
        int pos = atomicAdd(&g_cursor[e.y], 1);
        g_col[pos] = e.x;
    }
}

// ---------------------------------------------------------------------------
// Gather: one warp per node; agg[v] = x[v] + sum_{u in in(v)} x[u].
// No float atomics; all L2-resident reads. Fuses the "+x" init (no copy pass).
// ---------------------------------------------------------------------------
__global__ void __launch_bounds__(256)
gather_kernel(const float* __restrict__ x, float* __restrict__ agg) {
    int gw   = (blockIdx.x * blockDim.x + threadIdx.x) >> 5;
    int lane = threadIdx.x & 31;
    if (gw >= N_NODES) return;

    float4 acc0 = __ldg((const float4*)(x + (size_t)gw * DIM) + lane);
    float4 acc1 = make_float4(0.f, 0.f, 0.f, 0.f);

    int start = __ldg(&g_start[gw]);
    int deg   = __ldg(&g_deg[gw]);

    for (int i0 = 0; i0 < deg; i0 += 32) {
        int rem = deg - i0;
        int c = (lane < rem) ? __ldg(&g_col[start + i0 + lane]) : 0;
        int m = min(32, rem);
        int j = 0;
        for (; j + 1 < m; j += 2) {
            int s0 = __shfl_sync(0xffffffffu, c, j);
            int s1 = __shfl_sync(0xffffffffu, c, j + 1);
            float4 v0 = __ldg((const float4*)(x + (size_t)s0 * DIM) + lane);
            float4 v1 = __ldg((const float4*)(x + (size_t)s1 * DIM) + lane);
            acc0.x += v0.x; acc0.y += v0.y; acc0.z += v0.z; acc0.w += v0.w;
            acc1.x += v1.x; acc1.y += v1.y; acc1.z += v1.z; acc1.w += v1.w;
        }
        if (j < m) {
            int s0 = __shfl_sync(0xffffffffu, c, j);
            float4 v0 = __ldg((const float4*)(x + (size_t)s0 * DIM) + lane);
            acc0.x += v0.x; acc0.y += v0.y; acc0.z += v0.z; acc0.w += v0.w;
        }
    }
    acc0.x += acc1.x; acc0.y += acc1.y; acc0.z += acc1.z; acc0.w += acc1.w;
    *((float4*)(agg + (size_t)gw * DIM) + lane) = acc0;
}

// ---------------------------------------------------------------------------
// Layer-1 fused MLP (f32x2): Y = relu( relu(X*Wa + ba) * Wb + bb )
// ---------------------------------------------------------------------------
#define L1_SMEM_FLOATS (64*132 + 128*128 + 128*128)

__global__ void __launch_bounds__(256, 1)
gin_mlp128_kernel(const float* __restrict__ X,
                  const float* __restrict__ Wa, const float* __restrict__ ba,
                  const float* __restrict__ Wb, const float* __restrict__ bb,
                  float* __restrict__ Y) {
    extern __shared__ float sm[];
    float* Xs  = sm;                // [64][132] padded
    float* Was = sm + 64 * 132;     // [128][128]
    float* Wbs = Was + 128 * 128;   // [128][128]

    const int tid  = threadIdx.x;
    const int cg   = tid & 15;      // col group: cols [cg*8, cg*8+8)
    const int rg   = tid >> 4;      // row group: rows [rg*4, rg*4+4)
    const int base = blockIdx.x * 64;

    for (int idx = tid; idx < 64 * 32; idx += 256) {
        int r = idx >> 5, c4 = idx & 31;
        int row = base + r;
        float4 v = (row < N_NODES)
                       ? __ldg(((const float4*)(X + (size_t)row * DIM)) + c4)
                       : make_float4(0.f, 0.f, 0.f, 0.f);
        *(float4*)(Xs + r * 132 + c4 * 4) = v;
    }
    for (int idx = tid; idx < 4096; idx += 256) {
        ((float4*)Was)[idx] = __ldg(((const float4*)Wa) + idx);
        ((float4*)Wbs)[idx] = __ldg(((const float4*)Wb) + idx);
    }
    __syncthreads();

    u64 acc[4][4];   // 4 rows x 4 col-pairs (8 cols)

    // ---- stage 1: H = relu(X*Wa + ba) ----
    {
        ulonglong2 b01 = __ldg((const ulonglong2*)(ba + cg * 8));
        ulonglong2 b23 = __ldg((const ulonglong2*)(ba + cg * 8 + 4));
        #pragma unroll
        for (int i = 0; i < 4; i++) {
            acc[i][0] = b01.x; acc[i][1] = b01.y;
            acc[i][2] = b23.x; acc[i][3] = b23.y;
        }
    }
    #pragma unroll 4
    for (int k = 0; k < 128; k++) {
        ulonglong2 w01 = *(const ulonglong2*)(Was + k * 128 + cg * 8);
        ulonglong2 w23 = *(const ulonglong2*)(Was + k * 128 + cg * 8 + 4);
        #pragma unroll
        for (int i = 0; i < 4; i++) {
            u64 xp = bcast2(Xs[(rg * 4 + i) * 132 + k]);
            ffma2(acc[i][0], xp, w01.x);
            ffma2(acc[i][1], xp, w01.y);
            ffma2(acc[i][2], xp, w23.x);
            ffma2(acc[i][3], xp, w23.y);
        }
    }
    __syncthreads();
    #pragma unroll
    for (int i = 0; i < 4; i++) {
        float2 p0 = unpk(acc[i][0]), p1 = unpk(acc[i][1]);
        float2 p2 = unpk(acc[i][2]), p3 = unpk(acc[i][3]);
        float4 a0 = make_float4(fmaxf(p0.x,0.f), fmaxf(p0.y,0.f), fmaxf(p1.x,0.f), fmaxf(p1.y,0.f));
        float4 a1 = make_float4(fmaxf(p2.x,0.f), fmaxf(p2.y,0.f), fmaxf(p3.x,0.f), fmaxf(p3.y,0.f));
        *(float4*)(Xs + (rg * 4 + i) * 132 + cg * 8)     = a0;
        *(float4*)(Xs + (rg * 4 + i) * 132 + cg * 8 + 4) = a1;
    }
    __syncthreads();

    // ---- stage 2: Y = relu(H*Wb + bb) ----
    {
        ulonglong2 b01 = __ldg((const ulonglong2*)(bb + cg * 8));
        ulonglong2 b23 = __ldg((const ulonglong2*)(bb + cg * 8 + 4));
        #pragma unroll
        for (int i = 0; i < 4; i++) {
            acc[i][0] = b01.x; acc[i][1] = b01.y;
            acc[i][2] = b23.x; acc[i][3] = b23.y;
        }
    }
    #pragma unroll 4
    for (int k = 0; k < 128; k++) {
        ulonglong2 w01 = *(const ulonglong2*)(Wbs + k * 128 + cg * 8);
        ulonglong2 w23 = *(const ulonglong2*)(Wbs + k * 128 + cg * 8 + 4);
        #pragma unroll
        for (int i = 0; i < 4; i++) {
            u64 xp = bcast2(Xs[(rg * 4 + i) * 132 + k]);
            ffma2(acc[i][0], xp, w01.x);
            ffma2(acc[i][1], xp, w01.y);
            ffma2(acc[i][2], xp, w23.x);
            ffma2(acc[i][3], xp, w23.y);
        }
    }
    #pragma unroll
    for (int i = 0; i < 4; i++) {
        int row = base + rg * 4 + i;
        if (row < N_NODES) {
            float2 p0 = unpk(acc[i][0]), p1 = unpk(acc[i][1]);
            float2 p2 = unpk(acc[i][2]), p3 = unpk(acc[i][3]);
            float4 a0 = make_float4(fmaxf(p0.x,0.f), fmaxf(p0.y,0.f), fmaxf(p1.x,0.f), fmaxf(p1.y,0.f));
            float4 a1 = make_float4(fmaxf(p2.x,0.f), fmaxf(p2.y,0.f), fmaxf(p3.x,0.f), fmaxf(p3.y,0.f));
            *(float4*)(Y + (size_t)row * DIM + cg * 8)     = a0;
            *(float4*)(Y + (size_t)row * DIM + cg * 8 + 4) = a1;
        }
    }
}

// ---------------------------------------------------------------------------
// Layer-2 fused (f32x2): out = softmax( relu(X*W2a + b2a) * W2b + b2b )
// ---------------------------------------------------------------------------
#define L2_SMEM_FLOATS (128*129 + 128*40 + 40*40)

__global__ void __launch_bounds__(128)
layer2_kernel(const float* __restrict__ X,
              const float* __restrict__ Wa, const float* __restrict__ ba,
              const float* __restrict__ Wb, const float* __restrict__ bb,
              float* __restrict__ out) {
    extern __shared__ float sm[];
    float* Xs  = sm;                 // [128][129]
    float* Was = sm + 128 * 129;     // [128][40]
    float* Wbs = Was + 128 * 40;     // [40][40]

    const int tid  = threadIdx.x;
    const int base = blockIdx.x * 128;

    for (int idx = tid; idx < 128 * 32; idx += 128) {
        int r = idx >> 5, c4 = idx & 31;
        int row = base + r;
        float4 v = (row < N_NODES)
                       ? __ldg(((const float4*)(X + (size_t)row * DIM)) + c4)
                       : make_float4(0.f, 0.f, 0.f, 0.f);
        float* d = Xs + r * 129 + c4 * 4;
        d[0] = v.x; d[1] = v.y; d[2] = v.z; d[3] = v.w;
    }
    for (int idx = tid; idx < (128 * 40) / 4; idx += 128)
        ((float4*)Was)[idx] = __ldg(((const float4*)Wa) + idx);
    for (int idx = tid; idx < (40 * 40) / 4; idx += 128)
        ((float4*)Wbs)[idx] = __ldg(((const float4*)Wb) + idx);
    __syncthreads();

    const int row = base + tid;

    u64 z2[20];
    #pragma unroll
    for (int c = 0; c < 20; c++) z2[c] = __ldg((const u64*)ba + c);

    #pragma unroll 2
    for (int k = 0; k < 128; k++) {
        u64 xp = bcast2(Xs[tid * 129 + k]);
        const ulonglong2* wr = (const ulonglong2*)(Was + k * 40);
        #pragma unroll
        for (int c2 = 0; c2 < 10; c2++) {
            ulonglong2 w = wr[c2];
            ffma2(z2[c2 * 2],     xp, w.x);
            ffma2(z2[c2 * 2 + 1], xp, w.y);
        }
    }
    float z[NCLS];
    #pragma unroll
    for (int c = 0; c < 20; c++) {
        float2 p = unpk(z2[c]);
        z[c * 2]     = fmaxf(p.x, 0.f);
        z[c * 2 + 1] = fmaxf(p.y, 0.f);
    }

    u64 lg2[20];
    #pragma unroll
    for (int c = 0; c < 20; c++) lg2[c] = __ldg((const u64*)bb + c);
    #pragma unroll 4
    for (int j = 0; j < NCLS; j++) {
        u64 zp = bcast2(z[j]);
        const ulonglong2* wr = (const ulonglong2*)(Wbs + j * 40);
        #pragma unroll
        for (int c2 = 0; c2 < 10; c2++) {
            ulonglong2 w = wr[c2];
            ffma2(lg2[c2 * 2],     zp, w.x);
            ffma2(lg2[c2 * 2 + 1], zp, w.y);
        }
    }
    float lg[NCLS];
    #pragma unroll
    for (int c = 0; c < 20; c++) {
        float2 p = unpk(lg2[c]);
        lg[c * 2] = p.x; lg[c * 2 + 1] = p.y;
    }

    float m = lg[0];
    #pragma unroll
    for (int c = 1; c < NCLS; c++) m = fmaxf(m, lg[c]);
    float s = 0.f;
    #pragma unroll
    for (int c = 0; c < NCLS; c++) { lg[c] = expf(lg[c] - m); s += lg[c]; }
    float inv = 1.f / s;

    if (row < N_NODES) {
        #pragma unroll
        for (int c4 = 0; c4 < 10; c4++) {
            float4 v = make_float4(lg[c4*4+0]*inv, lg[c4*4+1]*inv,
                                   lg[c4*4+2]*inv, lg[c4*4+3]*inv);
            *(float4*)(out + (size_t)row * NCLS + c4 * 4) = v;
        }
    }
}

// ---------------------------------------------------------------------------
extern "C" void kernel_launch(void* const* d_in, const int* in_sizes, int n_in,
                              void* d_out, int out_size) {
    const float* x   = (const float*)d_in[0];
    const int*   ei  = (const int*)  d_in[1];
    const float* W1a = (const float*)d_in[2];
    const float* b1a = (const float*)d_in[3];
    const float* W1b = (const float*)d_in[4];
    const float* b1b = (const float*)d_in[5];
    const float* W2a = (const float*)d_in[6];
    const float* b2a = (const float*)d_in[7];
    const float* W2b = (const float*)d_in[8];
    const float* b2b = (const float*)d_in[9];
    float* out = (float*)d_out;

    float *agg = nullptr, *x1 = nullptr;
    cudaGetSymbolAddress((void**)&agg, g_agg);
    cudaGetSymbolAddress((void**)&x1,  g_x1);

    const size_t l1_smem = L1_SMEM_FLOATS * sizeof(float);
    const size_t l2_smem = L2_SMEM_FLOATS * sizeof(float);
    cudaFuncSetAttribute(gin_mlp128_kernel, cudaFuncAttributeMaxDynamicSharedMemorySize, (int)l1_smem);
    cudaFuncSetAttribute(layer2_kernel,     cudaFuncAttributeMaxDynamicSharedMemorySize, (int)l2_smem);

    const int edge_blocks = (N_EDGES + 255) / 256;       // 6250
    const int node_blocks = NB;                          // 391
    const int gth_blocks  = (N_NODES * 32 + 255) / 256;  // warp per node
    const int mlp_blocks  = (N_NODES + 63) / 64;
    const int l2_blocks   = (N_NODES + 127) / 128;

    // CSR build (once; serves both layers)
    zero_deg_kernel  <<<node_blocks, 256>>>();
    count_kernel     <<<edge_blocks, 256>>>((const int2*)ei);
    block_sum_kernel <<<node_blocks, 256>>>();
    top_scan_kernel  <<<1, 512>>>();
    final_scan_kernel<<<node_blocks, 256>>>();
    fill_kernel      <<<edge_blocks, 256>>>((const int2*)ei);

    // Layer 1
    gather_kernel    <<<gth_blocks, 256>>>(x, agg);
    gin_mlp128_kernel<<<mlp_blocks, 256, l1_smem>>>(agg, W1a, b1a, W1b, b1b, x1);

    // Layer 2
    gather_kernel    <<<gth_blocks, 256>>>(x1, agg);
    layer2_kernel    <<<l2_blocks, 128, l2_smem>>>(agg, W2a, b2a, W2b, b2b, out);
}